// round 12
// baseline (speedup 1.0000x reference)
#include <cuda_runtime.h>

#define KK 16
#define LL 64
#define BB 32768
#define ROWF4 256          // 256 float4 per element row
#define NPAIR (LL / 2)     // 32 digit pairs

__device__ __forceinline__ void cp16(unsigned dst, const float4* src) {
    asm volatile("cp.async.cg.shared.global [%0], [%1], 16;\n" :: "r"(dst), "l"(src));
}

// ROLE 0 = add (carry1 state), ROLE 1 = sub (borrow0 state, c reversed at unpack).
// Cyclic-16 convolution via CRT split x^16-1 = (x^8-1)(x^8+1):
//   Y = cyclic8(a_lo+a_hi, 0.5*(c_lo+c_hi)), Z = negacyclic8(a_lo-a_hi, 0.5*(c_lo-c_hi))
//   X[v] = Y[v]+Z[v], X[v+8] = Y[v]-Z[v]
template<int ROLE>
__device__ __forceinline__ void digit_math(
    const float4 Ain[4], const float4 Cin[4],
    float& t, float4* __restrict__ so)
{
    float a[16], c[16];
    #pragma unroll
    for (int w = 0; w < 4; ++w) {
        const float4 A = Ain[w], C = Cin[w];
        a[4*w+0] = A.x; a[4*w+1] = A.y; a[4*w+2] = A.z; a[4*w+3] = A.w;
        if (ROLE == 0) {
            c[4*w+0] = C.x; c[4*w+1] = C.y; c[4*w+2] = C.z; c[4*w+3] = C.w;
        } else {  // c'[j] = c_orig[15-j], free register renaming
            c[15-(4*w+0)] = C.x; c[15-(4*w+1)] = C.y;
            c[15-(4*w+2)] = C.z; c[15-(4*w+3)] = C.w;
        }
    }

    // S: add = P(i+j>=16) via suffix sums; sub = P(i<j) via prefix sums of reversed c
    float S = 0.f;
    if (ROLE == 0) {
        float Cs[16];
        Cs[15] = c[15];
        #pragma unroll
        for (int m = 14; m >= 1; --m) Cs[m] = Cs[m + 1] + c[m];
        #pragma unroll
        for (int i = 1; i < 16; ++i) S = fmaf(a[i], Cs[16 - i], S);
    } else {
        float Cp[15];
        Cp[0] = c[0];
        #pragma unroll
        for (int m = 1; m < 15; ++m) Cp[m] = Cp[m - 1] + c[m];
        #pragma unroll
        for (int i = 0; i < 15; ++i) S = fmaf(a[i], Cp[14 - i], S);
    }

    // ---- CRT pre-split ----
    float sa[8], da[8], sc[8], dc[8], dcn[8];
    #pragma unroll
    for (int i = 0; i < 8; ++i) {
        sa[i] = a[i] + a[i + 8];
        da[i] = a[i] - a[i + 8];
        const float tl = 0.5f * c[i];
        const float th = 0.5f * c[i + 8];
        sc[i]  = tl + th;
        dc[i]  = tl - th;
        dcn[i] = th - tl;
    }

    // cyclic-8: Y[v] = sum_{(i+j)&7=v} sa_i * sc_j   (64 FMA)
    float Y[8];
    #pragma unroll
    for (int v = 0; v < 8; ++v) Y[v] = 0.f;
    #pragma unroll
    for (int i = 0; i < 8; ++i) {
        #pragma unroll
        for (int j = 0; j < 8; ++j)
            Y[(i + j) & 7] = fmaf(sa[i], sc[j], Y[(i + j) & 7]);
    }

    // negacyclic-8: Z[v] = sum_{i+j=v} da*dc - sum_{i+j=v+8} da*dc   (64 FMA)
    float Z[8];
    #pragma unroll
    for (int v = 0; v < 8; ++v) Z[v] = 0.f;
    #pragma unroll
    for (int i = 0; i < 8; ++i) {
        #pragma unroll
        for (int j = 0; j < 8; ++j) {
            if (i + j < 8) Z[i + j]     = fmaf(da[i], dc[j],  Z[i + j]);
            else           Z[i + j - 8] = fmaf(da[i], dcn[j], Z[i + j - 8]);
        }
    }

    // ---- CRT reconstruction ----
    float X[16];
    #pragma unroll
    for (int v = 0; v < 8; ++v) {
        X[v]     = Y[v] + Z[v];
        X[v + 8] = Y[v] - Z[v];
    }

    // res[v] = (1-t)*X[v] + t*X[(v-1)&15]
    float r[16];
    #pragma unroll
    for (int v = 0; v < 16; ++v)
        r[v] = fmaf(t, X[(v + 15) & 15] - X[v], X[v]);

    const float base = (ROLE == 0) ? S : (1.f - S - X[15]);
    t = fmaf(t, X[15], base);

    #pragma unroll
    for (int w = 0; w < 4; ++w)
        so[w] = make_float4(r[4*w], r[4*w+1], r[4*w+2], r[4*w+3]);
}

// Block = 64 threads: warp 0 = add, warp 1 = sub, 32 shared elements.
// Register-pipelined smem reads, double-buffered cp.async staging.
__global__ __launch_bounds__(64) void bitop_kernel(
    const float4* __restrict__ op1, const float4* __restrict__ op2,
    float4* __restrict__ outa, float4* __restrict__ outs)
{
    __shared__ float4 sin[2][64][9];   // rows 0-31 op1, 32-63 op2
    __shared__ float4 sou[2][32][9];

    const int tid = threadIdx.x;
    const int wid = tid >> 5;      // 0 = add, 1 = sub
    const int ln  = tid & 31;
    const int ebase = blockIdx.x * 32;

    const int q8 = tid & 7;
    const int g8 = tid >> 3;

    unsigned sb[2];
    sb[0] = (unsigned)__cvta_generic_to_shared(&sin[0][0][0]);
    sb[1] = (unsigned)__cvta_generic_to_shared(&sin[1][0][0]);

    #define STAGE(b, p)                                                       \
        do {                                                                  \
            _Pragma("unroll")                                                 \
            for (int r = 0; r < 8; ++r) {                                     \
                const int row = g8 + 8 * r;                                   \
                const float4* src = ((row < 32) ? op1 : op2)                  \
                    + (size_t)(ebase + (row & 31)) * ROWF4                    \
                    + (size_t)(p) * 8 + q8;                                   \
                cp16(sb[b] + row * 144 + q8 * 16, src);                       \
            }                                                                 \
            asm volatile("cp.async.commit_group;\n" ::);                      \
        } while (0)

    STAGE(0, 0);
    asm volatile("cp.async.wait_group 0;\n" ::);
    __syncthreads();

    float4 A1[4], C1[4], A2[4], C2[4];
    #pragma unroll
    for (int w = 0; w < 4; ++w) {
        A1[w] = sin[0][ln][w];
        C1[w] = sin[0][32 + ln][w];
    }
    STAGE(1, 1);

    const int q4 = ln & 7;
    const int g4 = ln >> 3;
    float4* const optr = wid ? outs : outa;
    const size_t obase[4] = {
        (size_t)(ebase + g4)      * ROWF4, (size_t)(ebase + g4 + 4)  * ROWF4,
        (size_t)(ebase + g4 + 8)  * ROWF4, (size_t)(ebase + g4 + 12) * ROWF4 };

    float t = wid ? 1.f : 0.f;

    #pragma unroll 1
    for (int p = 0; p < NPAIR; ++p) {
        const int b = p & 1;

        // prefetch digit 2p+1 (same buffer, resident)
        #pragma unroll
        for (int w = 0; w < 4; ++w) {
            A2[w] = sin[b][ln][4 + w];
            C2[w] = sin[b][32 + ln][4 + w];
        }

        // compute digit 2p
        if (wid == 0) digit_math<0>(A1, C1, t, &sou[0][ln][0]);
        else          digit_math<1>(A1, C1, t, &sou[1][ln][0]);

        if (p < NPAIR - 1) {
            asm volatile("cp.async.wait_group 0;\n" ::);
            __syncthreads();
            #pragma unroll
            for (int w = 0; w < 4; ++w) {
                A1[w] = sin[b ^ 1][ln][w];
                C1[w] = sin[b ^ 1][32 + ln][w];
            }
            if (p + 2 < NPAIR) STAGE(b, p + 2);
        }

        // compute digit 2p+1
        if (wid == 0) digit_math<0>(A2, C2, t, &sou[0][ln][4]);
        else          digit_math<1>(A2, C2, t, &sou[1][ln][4]);
        __syncwarp();

        // full-128B coalesced stores of both digits
        const size_t po = (size_t)p * 8 + q4;
        #pragma unroll
        for (int r = 0; r < 4; ++r) {
            optr[obase[r] + po]                      = sou[wid][g4 + 4 * r][q4];
            optr[obase[r] + (size_t)16 * ROWF4 + po] = sou[wid][g4 + 4 * r + 16][q4];
        }
        __syncwarp();
    }
    #undef STAGE
}

extern "C" void kernel_launch(void* const* d_in, const int* in_sizes, int n_in,
                              void* d_out, int out_size)
{
    const float4* op1 = (const float4*)d_in[0];
    const float4* op2 = (const float4*)d_in[1];
    float* out = (float*)d_out;
    float4* outa = (float4*)out;
    float4* outs = (float4*)(out + (size_t)BB * LL * KK);

    bitop_kernel<<<BB / 32, 64>>>(op1, op2, outa, outs);
}

// round 13
// speedup vs baseline: 1.2249x; 1.2249x over previous
#include <cuda_runtime.h>

#define KK 16
#define LL 64
#define BB 32768
#define ROWF4 256          // 256 float4 per element row
#define NPAIR (LL / 2)     // 32 digit pairs

__device__ __forceinline__ void cp16(unsigned dst, const float4* src) {
    asm volatile("cp.async.cg.shared.global [%0], [%1], 16;\n" :: "r"(dst), "l"(src));
}

// ROLE 0 = add (carry1 state), ROLE 1 = sub (borrow0 state, c reversed at unpack).
// Cyclic-16 conv via CRT split, IN-PLACE butterflies (register-neutral):
//   a[i],a[i+8] <- a[i]+a[i+8], a[i]-a[i+8]
//   c[i],c[i+8] <- 0.5(c[i]+c[i+8]), 0.5(c[i]-c[i+8])
//   Y = cyclic8(a_lo', c_lo'); Z = negacyclic8(a_hi', c_hi')
//   X[v] = Y[v]+Z[v]; X[v+8] = Y[v]-Z[v]   (X overlays dead a[])
template<int ROLE>
__device__ __forceinline__ void digit_math(
    const float4 Ain[4], const float4 Cin[4],
    float& t, float4* __restrict__ so)
{
    float a[16], c[16];
    #pragma unroll
    for (int w = 0; w < 4; ++w) {
        const float4 A = Ain[w], C = Cin[w];
        a[4*w+0] = A.x; a[4*w+1] = A.y; a[4*w+2] = A.z; a[4*w+3] = A.w;
        if (ROLE == 0) {
            c[4*w+0] = C.x; c[4*w+1] = C.y; c[4*w+2] = C.z; c[4*w+3] = C.w;
        } else {  // c'[j] = c_orig[15-j], free register renaming
            c[15-(4*w+0)] = C.x; c[15-(4*w+1)] = C.y;
            c[15-(4*w+2)] = C.z; c[15-(4*w+3)] = C.w;
        }
    }

    // S first (uses original working c): add = P(i+j>=16); sub = P(i<j)
    float S = 0.f;
    if (ROLE == 0) {
        float Cs[16];
        Cs[15] = c[15];
        #pragma unroll
        for (int m = 14; m >= 1; --m) Cs[m] = Cs[m + 1] + c[m];
        #pragma unroll
        for (int i = 1; i < 16; ++i) S = fmaf(a[i], Cs[16 - i], S);
    } else {
        float Cp[15];
        Cp[0] = c[0];
        #pragma unroll
        for (int m = 1; m < 15; ++m) Cp[m] = Cp[m - 1] + c[m];
        #pragma unroll
        for (int i = 0; i < 15; ++i) S = fmaf(a[i], Cp[14 - i], S);
    }

    // ---- in-place CRT butterflies ----
    #pragma unroll
    for (int i = 0; i < 8; ++i) {
        const float lo = a[i], hi = a[i + 8];
        a[i]     = lo + hi;          // sa
        a[i + 8] = lo - hi;          // da
        const float th = 0.5f * c[i + 8];
        const float cl = c[i];
        c[i]     = fmaf(0.5f, cl,  th);   // sc (0.5 folded)
        c[i + 8] = fmaf(0.5f, cl, -th);   // dc (0.5 folded)
    }

    // cyclic-8 on (a[0..7], c[0..7]) and negacyclic-8 on (a[8..15], c[8..15]),
    // interleaved for ILP (16 independent accumulator chains of length 8)
    float Y[8], Z[8];
    #pragma unroll
    for (int v = 0; v < 8; ++v) { Y[v] = 0.f; Z[v] = 0.f; }
    #pragma unroll
    for (int i = 0; i < 8; ++i) {
        #pragma unroll
        for (int j = 0; j < 8; ++j) {
            Y[(i + j) & 7] = fmaf(a[i], c[j], Y[(i + j) & 7]);
            if (i + j < 8) Z[i + j]     = fmaf( a[8 + i], c[8 + j], Z[i + j]);
            else           Z[i + j - 8] = fmaf(-a[8 + i], c[8 + j], Z[i + j - 8]);
        }
    }

    // reconstruction into dead a[] registers
    #pragma unroll
    for (int v = 0; v < 8; ++v) {
        a[v]     = Y[v] + Z[v];
        a[v + 8] = Y[v] - Z[v];
    }

    // res[v] = (1-t)*X[v] + t*X[(v-1)&15]
    float r[16];
    #pragma unroll
    for (int v = 0; v < 16; ++v)
        r[v] = fmaf(t, a[(v + 15) & 15] - a[v], a[v]);

    const float base = (ROLE == 0) ? S : (1.f - S - a[15]);
    t = fmaf(t, a[15], base);

    #pragma unroll
    for (int w = 0; w < 4; ++w)
        so[w] = make_float4(r[4*w], r[4*w+1], r[4*w+2], r[4*w+3]);
}

// Block = 64 threads: warp 0 = add, warp 1 = sub, 32 shared elements.
// Register-pipelined smem reads, double-buffered cp.async staging.
__global__ __launch_bounds__(64, 7) void bitop_kernel(
    const float4* __restrict__ op1, const float4* __restrict__ op2,
    float4* __restrict__ outa, float4* __restrict__ outs)
{
    __shared__ float4 sin[2][64][9];   // rows 0-31 op1, 32-63 op2
    __shared__ float4 sou[2][32][9];

    const int tid = threadIdx.x;
    const int wid = tid >> 5;      // 0 = add, 1 = sub
    const int ln  = tid & 31;
    const int ebase = blockIdx.x * 32;

    const int q8 = tid & 7;
    const int g8 = tid >> 3;

    unsigned sb[2];
    sb[0] = (unsigned)__cvta_generic_to_shared(&sin[0][0][0]);
    sb[1] = (unsigned)__cvta_generic_to_shared(&sin[1][0][0]);

    #define STAGE(b, p)                                                       \
        do {                                                                  \
            _Pragma("unroll")                                                 \
            for (int r = 0; r < 8; ++r) {                                     \
                const int row = g8 + 8 * r;                                   \
                const float4* src = ((row < 32) ? op1 : op2)                  \
                    + (size_t)(ebase + (row & 31)) * ROWF4                    \
                    + (size_t)(p) * 8 + q8;                                   \
                cp16(sb[b] + row * 144 + q8 * 16, src);                       \
            }                                                                 \
            asm volatile("cp.async.commit_group;\n" ::);                      \
        } while (0)

    STAGE(0, 0);
    asm volatile("cp.async.wait_group 0;\n" ::);
    __syncthreads();

    float4 A1[4], C1[4], A2[4], C2[4];
    #pragma unroll
    for (int w = 0; w < 4; ++w) {
        A1[w] = sin[0][ln][w];
        C1[w] = sin[0][32 + ln][w];
    }
    STAGE(1, 1);

    const int q4 = ln & 7;
    const int g4 = ln >> 3;
    float4* const optr = wid ? outs : outa;
    const size_t obase[4] = {
        (size_t)(ebase + g4)      * ROWF4, (size_t)(ebase + g4 + 4)  * ROWF4,
        (size_t)(ebase + g4 + 8)  * ROWF4, (size_t)(ebase + g4 + 12) * ROWF4 };

    float t = wid ? 1.f : 0.f;

    #pragma unroll 1
    for (int p = 0; p < NPAIR; ++p) {
        const int b = p & 1;

        // prefetch digit 2p+1 (same buffer, resident)
        #pragma unroll
        for (int w = 0; w < 4; ++w) {
            A2[w] = sin[b][ln][4 + w];
            C2[w] = sin[b][32 + ln][4 + w];
        }

        // compute digit 2p
        if (wid == 0) digit_math<0>(A1, C1, t, &sou[0][ln][0]);
        else          digit_math<1>(A1, C1, t, &sou[1][ln][0]);

        if (p < NPAIR - 1) {
            asm volatile("cp.async.wait_group 0;\n" ::);
            __syncthreads();
            #pragma unroll
            for (int w = 0; w < 4; ++w) {
                A1[w] = sin[b ^ 1][ln][w];
                C1[w] = sin[b ^ 1][32 + ln][w];
            }
            if (p + 2 < NPAIR) STAGE(b, p + 2);
        }

        // compute digit 2p+1
        if (wid == 0) digit_math<0>(A2, C2, t, &sou[0][ln][4]);
        else          digit_math<1>(A2, C2, t, &sou[1][ln][4]);
        __syncwarp();

        // full-128B coalesced stores of both digits
        const size_t po = (size_t)p * 8 + q4;
        #pragma unroll
        for (int r = 0; r < 4; ++r) {
            optr[obase[r] + po]                      = sou[wid][g4 + 4 * r][q4];
            optr[obase[r] + (size_t)16 * ROWF4 + po] = sou[wid][g4 + 4 * r + 16][q4];
        }
        __syncwarp();
    }
    #undef STAGE
}

extern "C" void kernel_launch(void* const* d_in, const int* in_sizes, int n_in,
                              void* d_out, int out_size)
{
    const float4* op1 = (const float4*)d_in[0];
    const float4* op2 = (const float4*)d_in[1];
    float* out = (float*)d_out;
    float4* outa = (float4*)out;
    float4* outs = (float4*)(out + (size_t)BB * LL * KK);

    bitop_kernel<<<BB / 32, 64>>>(op1, op2, outa, outs);
}